// round 4
// baseline (speedup 1.0000x reference)
#include <cuda_runtime.h>
#include <cstdint>

#define B_    32
#define H_    128
#define W_    128
#define N_    1024
#define K_    49152          // 3*128*128
#define ROWS_ 384            // K rows of 128
#define SLABS_ 37            // 37*8 = 296 CTAs = 2/SM, one wave
#define NTB_  128            // n columns per CTA

// ---- device scratch (no allocations allowed) ----
__device__ float    g_gy [H_*N_];        // gy[h][n]
__device__ float    g_gxn[W_*N_];        // gx[w][n]*norm[n]
__device__ uint16_t g_xhi[B_*K_];        // x hi bf16
__device__ uint16_t g_xlo[B_*K_];        // x lo bf16
__device__ float    g_part[SLABS_*B_*N_];

// ---- smem layout (bytes) ----
#define SM_GXN 0                          // 128*128*4 = 65536
#define SM_GY  65536                      // up to 11 rows * 512B = 5632
#define SM_A   (65536 + 5632)             // [buf][term] 32*48B = 1536 each, 4 total
#define SM_B   (SM_A + 4*1536)            // [buf][term] 16*272B = 4352 each, 4 total
#define SMEM_TOTAL (SM_B + 4*4352)        // 94720 B

// ---- helpers ----
__device__ __forceinline__ uint32_t pack2(float lo, float hi){
    uint32_t d; asm("cvt.rn.bf16x2.f32 %0, %1, %2;" : "=r"(d) : "f"(hi), "f"(lo)); return d;
}
__device__ __forceinline__ uint32_t s2u(const void* p){
    return (uint32_t)__cvta_generic_to_shared(p);
}
__device__ __forceinline__ void ldsm_x4(uint32_t* r, uint32_t a){
    asm volatile("ldmatrix.sync.aligned.m8n8.x4.shared.b16 {%0,%1,%2,%3}, [%4];"
      : "=r"(r[0]),"=r"(r[1]),"=r"(r[2]),"=r"(r[3]) : "r"(a));
}
__device__ __forceinline__ void ldsm_x4t(uint32_t* r, uint32_t a){
    asm volatile("ldmatrix.sync.aligned.m8n8.x4.trans.shared.b16 {%0,%1,%2,%3}, [%4];"
      : "=r"(r[0]),"=r"(r[1]),"=r"(r[2]),"=r"(r[3]) : "r"(a));
}
__device__ __forceinline__ void mma_bf16(float* c, const uint32_t* a, uint32_t b0, uint32_t b1){
    asm volatile("mma.sync.aligned.m16n8k16.row.col.f32.bf16.bf16.f32 "
      "{%0,%1,%2,%3}, {%4,%5,%6,%7}, {%8,%9}, {%0,%1,%2,%3};"
      : "+f"(c[0]),"+f"(c[1]),"+f"(c[2]),"+f"(c[3])
      : "r"(a[0]),"r"(a[1]),"r"(a[2]),"r"(a[3]),"r"(b0),"r"(b1));
}

// ---- kernel 1: Gaussian tables, block per neuron ----
__global__ void build_tables(const float* __restrict__ mu_x, const float* __restrict__ mu_y,
                             const float* __restrict__ sg_x, const float* __restrict__ sg_y)
{
    __shared__ float red[8];
    int n = blockIdx.x, i = threadIdx.x;           // 128 threads, i = coordinate
    float mx = mu_x[n], my = mu_y[n];
    float isx = 1.f/sg_x[n], isy = 1.f/sg_y[n];
    float g  = (float)i * (1.f/127.f);
    float tx = (g - mx)*isx, ty = (g - my)*isy;
    float vx = expf(-0.5f*tx*tx), vy = expf(-0.5f*ty*ty);
    float sx2 = vx*vx, sy2 = vy*vy;
#pragma unroll
    for (int o = 16; o; o >>= 1){
        sx2 += __shfl_xor_sync(0xffffffffu, sx2, o);
        sy2 += __shfl_xor_sync(0xffffffffu, sy2, o);
    }
    if ((i&31)==0){ red[i>>5] = sx2; red[4+(i>>5)] = sy2; }
    __syncthreads();
    sx2 = red[0]+red[1]+red[2]+red[3];
    sy2 = red[4]+red[5]+red[6]+red[7];
    float nrm = sqrtf((float)(H_*W_)/(sx2*sy2));   // C cancels in normalization
    g_gxn[i*N_ + n] = vx*nrm;
    g_gy [i*N_ + n] = vy;
}

// ---- kernel 2: split x into bf16 hi/lo ----
__global__ void xsplit(const float* __restrict__ x)
{
    int i = blockIdx.x*256 + threadIdx.x;          // over B*K/4 float4s
    float4 v = ((const float4*)x)[i];
    uint32_t h0 = pack2(v.x, v.y);
    uint32_t h1 = pack2(v.z, v.w);
    float r0 = v.x - __uint_as_float(h0<<16);
    float r1 = v.y - __uint_as_float(h0 & 0xffff0000u);
    float r2 = v.z - __uint_as_float(h1<<16);
    float r3 = v.w - __uint_as_float(h1 & 0xffff0000u);
    ((uint2*)g_xhi)[i] = make_uint2(h0, h1);
    ((uint2*)g_xlo)[i] = make_uint2(pack2(r0,r1), pack2(r2,r3));
}

// ---- kernel 3: main masked MMA GEMM ----
__global__ __launch_bounds__(256, 2) void main_kernel(const float* __restrict__ wgt)
{
    extern __shared__ char smem[];
    float* gxn_s = (float*)(smem + SM_GXN);
    float* gy_s  = (float*)(smem + SM_GY);

    const int t     = threadIdx.x;
    const int slab  = blockIdx.x, ntile = blockIdx.y;
    const int nbase = ntile * NTB_;
    const int r0    = slab*ROWS_/SLABS_, r1 = (slab+1)*ROWS_/SLABS_;
    const int rows  = r1 - r0;
    const int nchunks = rows*8;

    // preload gxn slab [128 wcol x 128 n] and gy rows [rows x 128 n]
    for (int i = t; i < (W_*NTB_)/4; i += 256){
        int wc = i>>5, p = (i&31)*4;
        *(float4*)(gxn_s + wc*NTB_ + p) = *(const float4*)(g_gxn + wc*N_ + nbase + p);
    }
    for (int i = t; i < rows*32; i += 256){
        int rr = i>>5, p = (i&31)*4;
        int h = (r0 + rr) & (H_-1);
        *(float4*)(gy_s + rr*NTB_ + p) = *(const float4*)(g_gy + h*N_ + nbase + p);
    }

    const int krow = t>>4, nidx = t&15, n0 = nidx*8;   // B-convert role
    const int xrole = t>>6;                             // 0: stage xhi, 1: stage xlo
    const int xb = (t&63)>>1, xoff = t&1;               // b row, 8-half segment

    const int lane = t & 31, warp = t >> 5;
    const int mat = lane>>3, rowin = lane&7;
    const uint32_t aOff = (uint32_t)(((mat&1)*8 + rowin)*48 + (mat>>1)*16);
    const uint32_t bOff = (uint32_t)(((mat&1)*8 + rowin)*272 + warp*32 + (mat>>1)*16);
    const uint32_t smA = s2u(smem + SM_A), smB = s2u(smem + SM_B);

    // 2-deep register prefetch of weights + x
    float4 wA[2], wB[2];
    uint4  xv[2];

#define LDW(c, s) do { \
    int r_ = r0 + ((c)>>3); \
    size_t kg_ = (size_t)r_*W_ + ((c)&7)*16 + krow; \
    const float4* p_ = (const float4*)(wgt + kg_*N_ + nbase + n0); \
    wA[s] = p_[0]; wB[s] = p_[1]; } while(0)
#define LDX(c, s) do { \
    if (xrole < 2){ \
        int r_ = r0 + ((c)>>3); \
        int kb_ = r_*W_ + ((c)&7)*16; \
        const uint16_t* src_ = (xrole==0) ? g_xhi : g_xlo; \
        xv[s] = *(const uint4*)(src_ + (size_t)xb*K_ + kb_ + xoff*8); } } while(0)

    LDW(0,0); LDX(0,0);
    LDW(1,1); LDX(1,1);

    float acc[2][2][4];
#pragma unroll
    for (int a=0;a<2;a++)
#pragma unroll
        for (int b=0;b<2;b++)
#pragma unroll
            for (int q=0;q<4;q++) acc[a][b][q] = 0.f;

    __syncthreads();   // gxn_s / gy_s ready

    for (int c = 0; c < nchunks; ++c){
        const int buf = c & 1, s = c & 1;

        // ---- convert w -> masked bf16 hi/lo, STS into B tile ----
        {
            const int wcol = (c&7)*16 + krow;
            const int rr   = c>>3;
            float4 ga0 = *(float4*)(gxn_s + wcol*NTB_ + n0);
            float4 ga1 = *(float4*)(gxn_s + wcol*NTB_ + n0 + 4);
            float4 gy0 = *(float4*)(gy_s  + rr*NTB_  + n0);
            float4 gy1 = *(float4*)(gy_s  + rr*NTB_  + n0 + 4);
            float4 w0 = wA[s], w1 = wB[s];
            float wm[8];
            wm[0]=w0.x*ga0.x*gy0.x; wm[1]=w0.y*ga0.y*gy0.y;
            wm[2]=w0.z*ga0.z*gy0.z; wm[3]=w0.w*ga0.w*gy0.w;
            wm[4]=w1.x*ga1.x*gy1.x; wm[5]=w1.y*ga1.y*gy1.y;
            wm[6]=w1.z*ga1.z*gy1.z; wm[7]=w1.w*ga1.w*gy1.w;
            uint32_t h0 = pack2(wm[0],wm[1]), h1 = pack2(wm[2],wm[3]);
            uint32_t h2 = pack2(wm[4],wm[5]), h3 = pack2(wm[6],wm[7]);
            float l0 = wm[0]-__uint_as_float(h0<<16), l1 = wm[1]-__uint_as_float(h0&0xffff0000u);
            float l2 = wm[2]-__uint_as_float(h1<<16), l3 = wm[3]-__uint_as_float(h1&0xffff0000u);
            float l4 = wm[4]-__uint_as_float(h2<<16), l5 = wm[5]-__uint_as_float(h2&0xffff0000u);
            float l6 = wm[6]-__uint_as_float(h3<<16), l7 = wm[7]-__uint_as_float(h3&0xffff0000u);
            *(uint4*)(smem + SM_B + (buf*2+0)*4352 + krow*272 + n0*2)
                = make_uint4(h0,h1,h2,h3);
            *(uint4*)(smem + SM_B + (buf*2+1)*4352 + krow*272 + n0*2)
                = make_uint4(pack2(l0,l1), pack2(l2,l3), pack2(l4,l5), pack2(l6,l7));
            if (xrole < 2)
                *(uint4*)(smem + SM_A + (buf*2+xrole)*1536 + xb*48 + xoff*16) = xv[s];
        }

        // prefetch chunk c+2 (slot s is free after the reads above)
        if (c+2 < nchunks){ LDW(c+2, s); LDX(c+2, s); }

        __syncthreads();

        // ---- fragments + 12 MMAs ----
        uint32_t Ah0[4], Ah1[4], Al0[4], Al1[4], Bh[4], Bl[4];
        uint32_t aH = smA + (buf*2+0)*1536 + aOff;
        uint32_t aL = smA + (buf*2+1)*1536 + aOff;
        ldsm_x4 (Ah0, aH);        ldsm_x4 (Ah1, aH + 768);
        ldsm_x4 (Al0, aL);        ldsm_x4 (Al1, aL + 768);
        ldsm_x4t(Bh,  smB + (buf*2+0)*4352 + bOff);
        ldsm_x4t(Bl,  smB + (buf*2+1)*4352 + bOff);

        mma_bf16(acc[0][0], Ah0, Bh[0], Bh[1]);
        mma_bf16(acc[0][1], Ah0, Bh[2], Bh[3]);
        mma_bf16(acc[1][0], Ah1, Bh[0], Bh[1]);
        mma_bf16(acc[1][1], Ah1, Bh[2], Bh[3]);
        mma_bf16(acc[0][0], Ah0, Bl[0], Bl[1]);
        mma_bf16(acc[0][1], Ah0, Bl[2], Bl[3]);
        mma_bf16(acc[1][0], Ah1, Bl[0], Bl[1]);
        mma_bf16(acc[1][1], Ah1, Bl[2], Bl[3]);
        mma_bf16(acc[0][0], Al0, Bh[0], Bh[1]);
        mma_bf16(acc[0][1], Al0, Bh[2], Bh[3]);
        mma_bf16(acc[1][0], Al1, Bh[0], Bh[1]);
        mma_bf16(acc[1][1], Al1, Bh[2], Bh[3]);
    }
#undef LDW
#undef LDX

    // ---- epilogue: partials ----
    const int grp = lane>>2, tg = lane&3;
    float* pp = g_part + (size_t)slab*(B_*N_);
#pragma unroll
    for (int mt = 0; mt < 2; ++mt)
#pragma unroll
        for (int nb = 0; nb < 2; ++nb){
            int b = mt*16 + grp;
            int n = nbase + warp*16 + nb*8 + tg*2;
            *(float2*)(pp + (size_t)b*N_ + n)     = make_float2(acc[mt][nb][0], acc[mt][nb][1]);
            *(float2*)(pp + (size_t)(b+8)*N_ + n) = make_float2(acc[mt][nb][2], acc[mt][nb][3]);
        }
}

// ---- kernel 4: deterministic split-K reduction ----
__global__ void reduce_k(float* __restrict__ out)
{
    int i = blockIdx.x*256 + threadIdx.x;   // 0 .. B*N-1
    float s = 0.f;
#pragma unroll 1
    for (int j = 0; j < SLABS_; ++j)
        s += g_part[(size_t)j*(B_*N_) + i];
    out[i] = s;
}

extern "C" void kernel_launch(void* const* d_in, const int* in_sizes, int n_in,
                              void* d_out, int out_size)
{
    const float* x   = (const float*)d_in[0];
    const float* mux = (const float*)d_in[1];
    const float* muy = (const float*)d_in[2];
    const float* sx  = (const float*)d_in[3];
    const float* sy  = (const float*)d_in[4];
    const float* wgt = (const float*)d_in[5];

    cudaFuncSetAttribute(main_kernel, cudaFuncAttributeMaxDynamicSharedMemorySize, SMEM_TOTAL);

    build_tables<<<N_, 128>>>(mux, muy, sx, sy);
    xsplit<<<(B_*K_/4)/256, 256>>>(x);
    main_kernel<<<dim3(SLABS_, 8), 256, SMEM_TOTAL>>>(wgt);
    reduce_k<<<(B_*N_)/256, 256>>>((float*)d_out);
}

// round 6
// speedup vs baseline: 1.1495x; 1.1495x over previous
#include <cuda_runtime.h>
#include <cuda_fp16.h>
#include <cstdint>

#define B_ 32
#define H_ 128
#define W_ 128
#define N_ 1024
#define K_ 49152
#define ROWS_ 384
#define SLABS_ 37
#define NTB_ 128

__device__ float    g_gy [H_*N_];
__device__ float    g_gxn[W_*N_];
__device__ uint16_t g_xh [B_*K_];
__device__ float    g_part[SLABS_*B_*N_];

// smem layout (bytes)
#define SM_GXN 0                    // 65536
#define SM_GY  65536                // 5632
#define SM_A   (65536+5632)         // 2 bufs * 1536 (32 rows * 48B)
#define SM_B   (SM_A+2*1536)        // 2 bufs * 4352 (16 rows * 272B)
#define SMEM_TOTAL (SM_B+2*4352)    // 82944

__device__ __forceinline__ uint32_t s2u(const void* p){
    return (uint32_t)__cvta_generic_to_shared(p);
}
__device__ __forceinline__ uint32_t packh2(float a, float b){
    __half2 h = __floats2half2_rn(a, b);
    return *(uint32_t*)&h;
}
__device__ __forceinline__ void ldsm_x4(uint32_t* r, uint32_t a){
    asm volatile("ldmatrix.sync.aligned.m8n8.x4.shared.b16 {%0,%1,%2,%3}, [%4];"
      : "=r"(r[0]),"=r"(r[1]),"=r"(r[2]),"=r"(r[3]) : "r"(a));
}
__device__ __forceinline__ void ldsm_x4t(uint32_t* r, uint32_t a){
    asm volatile("ldmatrix.sync.aligned.m8n8.x4.trans.shared.b16 {%0,%1,%2,%3}, [%4];"
      : "=r"(r[0]),"=r"(r[1]),"=r"(r[2]),"=r"(r[3]) : "r"(a));
}
__device__ __forceinline__ void mma_f16(float* c, const uint32_t* a, uint32_t b0, uint32_t b1){
    asm volatile("mma.sync.aligned.m16n8k16.row.col.f32.f16.f16.f32 "
      "{%0,%1,%2,%3}, {%4,%5,%6,%7}, {%8,%9}, {%0,%1,%2,%3};"
      : "+f"(c[0]),"+f"(c[1]),"+f"(c[2]),"+f"(c[3])
      : "r"(a[0]),"r"(a[1]),"r"(a[2]),"r"(a[3]),"r"(b0),"r"(b1));
}

// ---- kernel 1: Gaussian tables, block per neuron ----
__global__ void build_tables(const float* __restrict__ mu_x, const float* __restrict__ mu_y,
                             const float* __restrict__ sg_x, const float* __restrict__ sg_y)
{
    __shared__ float red[8];
    int n = blockIdx.x, i = threadIdx.x;
    float mx = mu_x[n], my = mu_y[n], isx = 1.f/sg_x[n], isy = 1.f/sg_y[n];
    float g = (float)i*(1.f/127.f);
    float tx = (g-mx)*isx, ty = (g-my)*isy;
    float vx = expf(-0.5f*tx*tx), vy = expf(-0.5f*ty*ty);
    float sx2 = vx*vx, sy2 = vy*vy;
#pragma unroll
    for (int o=16;o;o>>=1){ sx2 += __shfl_xor_sync(~0u,sx2,o); sy2 += __shfl_xor_sync(~0u,sy2,o); }
    if ((i&31)==0){ red[i>>5]=sx2; red[4+(i>>5)]=sy2; }
    __syncthreads();
    sx2 = red[0]+red[1]+red[2]+red[3]; sy2 = red[4]+red[5]+red[6]+red[7];
    float nrm = sqrtf((float)(H_*W_)/(sx2*sy2));   // C cancels in normalization
    g_gxn[i*N_+n] = vx*nrm;  g_gy[i*N_+n] = vy;
}

// ---- kernel 2: x -> fp16 ----
__global__ void xhalf(const float* __restrict__ x)
{
    int i = blockIdx.x*256 + threadIdx.x;          // B*K/4 float4s
    float4 v = ((const float4*)x)[i];
    ((uint2*)g_xh)[i] = make_uint2(packh2(v.x,v.y), packh2(v.z,v.w));
}

// ---- kernel 3: main masked fp16 MMA GEMM ----
__global__ __launch_bounds__(256,2) void main_kernel(const float* __restrict__ wgt)
{
    extern __shared__ char smem[];
    float* gxn_s = (float*)(smem + SM_GXN);
    float* gy_s  = (float*)(smem + SM_GY);

    const int t = threadIdx.x, lane = t&31, warp = t>>5;
    const int slab = blockIdx.x, nbase = blockIdx.y*NTB_;
    const int r0 = slab*ROWS_/SLABS_, rows = (slab+1)*ROWS_/SLABS_ - r0;
    const int nch = rows*8, kbase = r0*W_;

    // preload gxn [128w x 128n] and gy rows
    for (int i = t; i < (W_*NTB_)/4; i += 256){
        int wc = i>>5, p = (i&31)*4;
        *(float4*)(gxn_s + wc*NTB_ + p) = *(const float4*)(g_gxn + wc*N_ + nbase + p);
    }
    for (int i = t; i < rows*32; i += 256){
        int rr = i>>5, p = (i&31)*4, h = (r0+rr)&(H_-1);
        *(float4*)(gy_s + rr*NTB_ + p) = *(const float4*)(g_gy + h*N_ + nbase + p);
    }

    const int klocal = t>>4, nseg = t&15, n0 = nseg*8;   // conversion role
    const int xb = t>>1, xs = t&1;                        // A-staging role (t<64)
    const int mat = lane>>3, rowin = lane&7;
    const uint32_t aOff = (uint32_t)(((mat&1)*8 + rowin)*48 + (mat>>1)*16);
    const uint32_t bOff = (uint32_t)(((mat&1)*8 + rowin)*272 + warp*32 + (mat>>1)*16);
    const uint32_t smA = s2u(smem + SM_A), smB = s2u(smem + SM_B);

    float4 wa[2][2];  uint4 xv[2];
#define LDW(c,s) do { size_t kg = (size_t)(kbase + (c)*16 + klocal); \
    const float4* p_ = (const float4*)(wgt + kg*N_ + nbase + n0); \
    wa[s][0] = p_[0]; wa[s][1] = p_[1]; } while(0)
#define LDX(c,s) do { if (t < 64) \
    xv[s] = *(const uint4*)(g_xh + (size_t)xb*K_ + kbase + (c)*16 + xs*8); } while(0)
    LDW(0,0); LDX(0,0); LDW(1,1); LDX(1,1);

    float acc[2][2][4];
#pragma unroll
    for (int a=0;a<2;a++)
#pragma unroll
      for (int b=0;b<2;b++)
#pragma unroll
        for (int q=0;q<4;q++) acc[a][b][q] = 0.f;

    __syncthreads();   // tables ready

    for (int c = 0; c < nch; ++c){
        const int buf = c & 1, s = c & 1;
        {   // masked fp16 weights -> B smem
            const float* gxp = gxn_s + ((c&7)*16 + klocal)*NTB_ + n0;
            const float* gyp = gy_s + (c>>3)*NTB_ + n0;
            float4 w0 = wa[s][0], w1 = wa[s][1];
            float m0=w0.x*gxp[0]*gyp[0], m1=w0.y*gxp[1]*gyp[1];
            float m2=w0.z*gxp[2]*gyp[2], m3=w0.w*gxp[3]*gyp[3];
            float m4=w1.x*gxp[4]*gyp[4], m5=w1.y*gxp[5]*gyp[5];
            float m6=w1.z*gxp[6]*gyp[6], m7=w1.w*gxp[7]*gyp[7];
            *(uint4*)(smem + SM_B + buf*4352 + klocal*272 + nseg*16)
                = make_uint4(packh2(m0,m1), packh2(m2,m3), packh2(m4,m5), packh2(m6,m7));
            if (t < 64)
                *(uint4*)(smem + SM_A + buf*1536 + xb*48 + xs*16) = xv[s];
        }
        if (c+2 < nch){ LDW(c+2,s); LDX(c+2,s); }
        __syncthreads();

        uint32_t A0[4], A1[4], Bv[4];
        ldsm_x4 (A0, smA + buf*1536 + aOff);
        ldsm_x4 (A1, smA + buf*1536 + 768 + aOff);
        ldsm_x4t(Bv, smB + buf*4352 + bOff);
        mma_f16(acc[0][0], A0, Bv[0], Bv[1]);
        mma_f16(acc[0][1], A0, Bv[2], Bv[3]);
        mma_f16(acc[1][0], A1, Bv[0], Bv[1]);
        mma_f16(acc[1][1], A1, Bv[2], Bv[3]);
    }
#undef LDW
#undef LDX

    // epilogue: partials (validated mapping)
    const int grp = lane>>2, tg = lane&3;
    float* pp = g_part + (size_t)slab*(B_*N_);
#pragma unroll
    for (int mt = 0; mt < 2; ++mt)
#pragma unroll
        for (int nb = 0; nb < 2; ++nb){
            int b = mt*16 + grp;
            int n = nbase + warp*16 + nb*8 + tg*2;
            *(float2*)(pp + (size_t)b*N_ + n)     = make_float2(acc[mt][nb][0], acc[mt][nb][1]);
            *(float2*)(pp + (size_t)(b+8)*N_ + n) = make_float2(acc[mt][nb][2], acc[mt][nb][3]);
        }
}

// ---- kernel 4: split-K reduce, float4 + full unroll ----
__global__ void reduce_k(float* __restrict__ out)
{
    int i = blockIdx.x*256 + threadIdx.x;   // B*N/4 float4s
    float4 s = make_float4(0.f,0.f,0.f,0.f);
#pragma unroll
    for (int j = 0; j < SLABS_; ++j){
        float4 v = ((const float4*)g_part)[(size_t)j*(B_*N_/4) + i];
        s.x += v.x; s.y += v.y; s.z += v.z; s.w += v.w;
    }
    ((float4*)out)[i] = s;
}

extern "C" void kernel_launch(void* const* d_in, const int* in_sizes, int n_in,
                              void* d_out, int out_size)
{
    const float* x   = (const float*)d_in[0];
    const float* mux = (const float*)d_in[1];
    const float* muy = (const float*)d_in[2];
    const float* sx  = (const float*)d_in[3];
    const float* sy  = (const float*)d_in[4];
    const float* wgt = (const float*)d_in[5];
    cudaFuncSetAttribute(main_kernel, cudaFuncAttributeMaxDynamicSharedMemorySize, SMEM_TOTAL);
    build_tables<<<N_, 128>>>(mux, muy, sx, sy);
    xhalf<<<(B_*K_/4)/256, 256>>>(x);
    main_kernel<<<dim3(SLABS_, 8), 256, SMEM_TOTAL>>>(wgt);
    reduce_k<<<(B_*N_/4)/256, 256>>>((float*)d_out);
}

// round 7
// speedup vs baseline: 2.1077x; 1.8336x over previous
#include <cuda_runtime.h>
#include <cuda_fp16.h>
#include <cstdint>

#define B_ 32
#define H_ 128
#define W_ 128
#define N_ 1024
#define K_ 49152
#define ROWS_ 384
#define SLABS_ 37
#define NTB_ 128

__device__ float    g_gy [H_*N_];
__device__ float    g_gxn[W_*N_];
__device__ uint16_t g_xh [B_*K_];
__device__ float    g_part[SLABS_*B_*N_];

// smem layout (bytes)
#define SM_GXN 0                     // 65536
#define SM_GY  65536                 // 11 rows * 512 = 5632
#define ACS    1568                  // A chunk stride (32 rows * 48B + 32 pad)
#define ABUF   (8*ACS)               // 12544 per A group buffer
#define SM_A   (65536+5632)          // 2 bufs
#define SM_B   (SM_A + 2*ABUF)      // 8 warps * 2 bufs * 768B
#define SMEM_TOTAL (SM_B + 16*768)   // 108544

__device__ __forceinline__ uint32_t s2u(const void* p){
    return (uint32_t)__cvta_generic_to_shared(p);
}
__device__ __forceinline__ uint32_t packh2(float a, float b){
    __half2 h = __floats2half2_rn(a, b);
    return *(uint32_t*)&h;
}
__device__ __forceinline__ void ldsm_x4(uint32_t* r, uint32_t a){
    asm volatile("ldmatrix.sync.aligned.m8n8.x4.shared.b16 {%0,%1,%2,%3}, [%4];"
      : "=r"(r[0]),"=r"(r[1]),"=r"(r[2]),"=r"(r[3]) : "r"(a));
}
__device__ __forceinline__ void ldsm_x4t(uint32_t* r, uint32_t a){
    asm volatile("ldmatrix.sync.aligned.m8n8.x4.trans.shared.b16 {%0,%1,%2,%3}, [%4];"
      : "=r"(r[0]),"=r"(r[1]),"=r"(r[2]),"=r"(r[3]) : "r"(a));
}
__device__ __forceinline__ void mma_f16(float* c, const uint32_t* a, uint32_t b0, uint32_t b1){
    asm volatile("mma.sync.aligned.m16n8k16.row.col.f32.f16.f16.f32 "
      "{%0,%1,%2,%3}, {%4,%5,%6,%7}, {%8,%9}, {%0,%1,%2,%3};"
      : "+f"(c[0]),"+f"(c[1]),"+f"(c[2]),"+f"(c[3])
      : "r"(a[0]),"r"(a[1]),"r"(a[2]),"r"(a[3]),"r"(b0),"r"(b1));
}

// ---- kernel 1: Gaussian tables ----
__global__ void build_tables(const float* __restrict__ mu_x, const float* __restrict__ mu_y,
                             const float* __restrict__ sg_x, const float* __restrict__ sg_y)
{
    __shared__ float red[8];
    int n = blockIdx.x, i = threadIdx.x;
    float mx = mu_x[n], my = mu_y[n], isx = 1.f/sg_x[n], isy = 1.f/sg_y[n];
    float g = (float)i*(1.f/127.f);
    float tx = (g-mx)*isx, ty = (g-my)*isy;
    float vx = expf(-0.5f*tx*tx), vy = expf(-0.5f*ty*ty);
    float sx2 = vx*vx, sy2 = vy*vy;
#pragma unroll
    for (int o=16;o;o>>=1){ sx2 += __shfl_xor_sync(~0u,sx2,o); sy2 += __shfl_xor_sync(~0u,sy2,o); }
    if ((i&31)==0){ red[i>>5]=sx2; red[4+(i>>5)]=sy2; }
    __syncthreads();
    sx2 = red[0]+red[1]+red[2]+red[3]; sy2 = red[4]+red[5]+red[6]+red[7];
    float nrm = sqrtf((float)(H_*W_)/(sx2*sy2));   // C cancels
    g_gxn[i*N_+n] = vx*nrm;  g_gy[i*N_+n] = vy;
}

// ---- kernel 2: x -> fp16 ----
__global__ void xhalf(const float* __restrict__ x)
{
    int i = blockIdx.x*256 + threadIdx.x;
    float4 v = ((const float4*)x)[i];
    ((uint2*)g_xh)[i] = make_uint2(packh2(v.x,v.y), packh2(v.z,v.w));
}

// ---- kernel 3: warp-autonomous masked fp16 MMA GEMM ----
__global__ __launch_bounds__(256,2) void main_kernel(const float* __restrict__ wgt)
{
    extern __shared__ char smem[];
    float* gxn_s = (float*)(smem + SM_GXN);
    float* gy_s  = (float*)(smem + SM_GY);

    const int t = threadIdx.x, lane = t&31, w = t>>5;
    const int slab = blockIdx.x, nbase = blockIdx.y*NTB_;
    const int r0 = slab*ROWS_/SLABS_, rows = (slab+1)*ROWS_/SLABS_ - r0;
    const int nch = rows*8, kbase = r0*W_;

    // preload gxn [128w x 128n] and gy rows
    for (int i = t; i < (W_*NTB_)/4; i += 256){
        int wc = i>>5, p = (i&31)*4;
        *(float4*)(gxn_s + wc*NTB_ + p) = *(const float4*)(g_gxn + wc*N_ + nbase + p);
    }
    for (int i = t; i < rows*32; i += 256){
        int rr = i>>5, p = (i&31)*4, h = (r0+rr)&(H_-1);
        *(float4*)(gy_s + rr*NTB_ + p) = *(const float4*)(g_gy + h*N_ + nbase + p);
    }

    // per-warp convert roles: lane -> (kq = lane>>2 in 0..7, q = lane&3)
    const int kq = lane>>2, q = lane&3;
    const int nq = w*16 + q*4;                 // n offset within CTA tile
    const float* wbase = wgt + (size_t)nbase + nq;
    // A staging role (all 256 threads): b row, 16B segment
    const int bA = t>>3, hA = t&7;
    // ldsm offsets (48B row stride, validated mapping)
    const int mat = lane>>3, rowin = lane&7;
    const uint32_t aOff = (uint32_t)(((mat&1)*8 + rowin)*48 + (mat>>1)*16);
    const uint32_t bOff = (uint32_t)(((mat&1)*8 + rowin)*48 + (mat>>1)*16);
    const uint32_t smA = s2u(smem + SM_A);
    const uint32_t smBw = s2u(smem + SM_B) + w*1536;
    char* bwp = smem + SM_B + w*1536;

    float4 wa[4][2];
#define LDW(c,s) do { if ((c) < nch){ \
    const float* p_ = wbase + (size_t)(kbase + (c)*16 + kq)*N_; \
    wa[s][0] = *(const float4*)(p_); wa[s][1] = *(const float4*)(p_ + 8*N_); } } while(0)

    // prologue: A group 0, weights chunks 0..3
    {
        const uint16_t* xp = g_xh + (size_t)bA*K_ + (size_t)r0*W_;
        uint4 a0 = *(const uint4*)(xp + hA*8);
        uint4 a1 = *(const uint4*)(xp + 64 + hA*8);
        *(uint4*)(smem + SM_A + (hA>>1)*ACS + bA*48 + (hA&1)*16) = a0;
        *(uint4*)(smem + SM_A + (4+(hA>>1))*ACS + bA*48 + (hA&1)*16) = a1;
    }
    LDW(0,0); LDW(1,1); LDW(2,2); LDW(3,3);

    float acc[2][2][4];
#pragma unroll
    for (int a=0;a<2;a++)
#pragma unroll
      for (int b=0;b<2;b++)
#pragma unroll
        for (int p=0;p<4;p++) acc[a][b][p] = 0.f;

    __syncthreads();   // tables + A buf0 ready

    int ab = 0;
    for (int g = 0; g < rows; ++g){
        const bool more = (g+1 < rows);
        uint4 av0, av1;
        if (more){
            const uint16_t* xp = g_xh + (size_t)bA*K_ + (size_t)(r0+g+1)*W_;
            av0 = *(const uint4*)(xp + hA*8);
            av1 = *(const uint4*)(xp + 64 + hA*8);
        }
        const float4 gyv = *(const float4*)(gy_s + g*NTB_ + nq);

#pragma unroll
        for (int cc = 0; cc < 8; ++cc){
            const int c = g*8 + cc, s = c&3, bb = c&1;
            // convert 8 weights -> masked fp16, STS to private B tile
            const float* gx0 = gxn_s + (cc*16 + kq)*NTB_ + nq;
            float4 ga = *(const float4*)gx0;
            float4 gb = *(const float4*)(gx0 + 8*NTB_);
            float4 w0 = wa[s][0], w1 = wa[s][1];
            uint2 lo = make_uint2(packh2(w0.x*ga.x*gyv.x, w0.y*ga.y*gyv.y),
                                  packh2(w0.z*ga.z*gyv.z, w0.w*ga.w*gyv.w));
            uint2 hi = make_uint2(packh2(w1.x*gb.x*gyv.x, w1.y*gb.y*gyv.y),
                                  packh2(w1.z*gb.z*gyv.z, w1.w*gb.w*gyv.w));
            *(uint2*)(bwp + bb*768 + kq*48 + q*8)     = lo;
            *(uint2*)(bwp + bb*768 + (kq+8)*48 + q*8) = hi;
            LDW(c+4, s);
            __syncwarp();

            uint32_t A0[4], A1[4], Bv[4];
            const uint32_t aBase = smA + ab*ABUF + cc*ACS + aOff;
            ldsm_x4 (A0, aBase);
            ldsm_x4 (A1, aBase + 768);
            ldsm_x4t(Bv, smBw + bb*768 + bOff);
            mma_f16(acc[0][0], A0, Bv[0], Bv[1]);
            mma_f16(acc[0][1], A0, Bv[2], Bv[3]);
            mma_f16(acc[1][0], A1, Bv[0], Bv[1]);
            mma_f16(acc[1][1], A1, Bv[2], Bv[3]);
        }
        if (more){
            char* ad = smem + SM_A + (ab^1)*ABUF;
            *(uint4*)(ad + (hA>>1)*ACS + bA*48 + (hA&1)*16)     = av0;
            *(uint4*)(ad + (4+(hA>>1))*ACS + bA*48 + (hA&1)*16) = av1;
        }
        __syncthreads();
        ab ^= 1;
    }
#undef LDW

    // epilogue: partials (validated mapping), warp owns n slice w*16..+15
    const int grp = lane>>2, tg = lane&3;
    float* pp = g_part + (size_t)slab*(B_*N_);
#pragma unroll
    for (int mt = 0; mt < 2; ++mt)
#pragma unroll
        for (int nb = 0; nb < 2; ++nb){
            int b = mt*16 + grp;
            int n = nbase + w*16 + nb*8 + tg*2;
            *(float2*)(pp + (size_t)b*N_ + n)     = make_float2(acc[mt][nb][0], acc[mt][nb][1]);
            *(float2*)(pp + (size_t)(b+8)*N_ + n) = make_float2(acc[mt][nb][2], acc[mt][nb][3]);
        }
}

// ---- kernel 4: split-K reduce (full grid, coalesced, unrolled) ----
__global__ void reduce_k(float* __restrict__ out)
{
    int i = blockIdx.x*256 + threadIdx.x;   // 0..B*N-1, grid=128
    float s = 0.f;
#pragma unroll
    for (int j = 0; j < SLABS_; ++j)
        s += g_part[j*(B_*N_) + i];
    out[i] = s;
}

extern "C" void kernel_launch(void* const* d_in, const int* in_sizes, int n_in,
                              void* d_out, int out_size)
{
    const float* x   = (const float*)d_in[0];
    const float* mux = (const float*)d_in[1];
    const float* muy = (const float*)d_in[2];
    const float* sx  = (const float*)d_in[3];
    const float* sy  = (const float*)d_in[4];
    const float* wgt = (const float*)d_in[5];
    cudaFuncSetAttribute(main_kernel, cudaFuncAttributeMaxDynamicSharedMemorySize, SMEM_TOTAL);
    build_tables<<<N_, 128>>>(mux, muy, sx, sy);
    xhalf<<<(B_*K_/4)/256, 256>>>(x);
    main_kernel<<<dim3(SLABS_, 8), 256, SMEM_TOTAL>>>(wgt);
    reduce_k<<<(B_*N_)/256, 256>>>((float*)d_out);
}